// round 12
// baseline (speedup 1.0000x reference)
#include <cuda_runtime.h>
#include <cuda_fp16.h>
#include <math.h>

#define NN_MAX 100000
#define EE_MAX 1600000
#define DF 128

#define SCAN_T 256
#define SCAN_C 4
#define SCAN_TILE (SCAN_T * SCAN_C)
#define SCAN_NBMAX ((NN_MAX + 1 + SCAN_TILE - 1) / SCAN_TILE + 1)

#define LDA 36                       // u32 row stride in smem (conflict-free)
#define CHUNK_BYTES (128 * LDA * 4)  // 18432 B per 128-row chunk
#define GEMM_SMEM (4 * CHUNK_BYTES)  // As[2] + Ws[2]
#define LSM_SMEM (2 * CHUNK_BYTES + 2 * (64 * LDA * 4))

// ---------------- scratch ----------------
__device__ int   g_idx64;
__device__ int   g_cnt[NN_MAX];
__device__ int   g_rowptr[NN_MAX + 1];
__device__ int   g_cursor[NN_MAX];
__device__ int   g_srcs[EE_MAX];
__device__ float g_dinv[NN_MAX];
__device__ int   g_bsum[SCAN_NBMAX];
__device__ int   g_boff[SCAN_NBMAX];
__device__ __half g_z0h[(size_t)NN_MAX * DF];
__device__ __half g_z1h[(size_t)NN_MAX * DF];
__device__ __half g_zsh[(size_t)NN_MAX * DF];   // xh staging
__device__ __half g_wh[448 * DF];               // W1|W2|fcW1|fcW2 fp16
__device__ float g_zs[(size_t)NN_MAX * DF];
__device__ float g_res[(size_t)NN_MAX * 64];
__device__ float g_zerob[DF];

// ---------------- helpers ----------------
__device__ __forceinline__ long long ldidx(const void* p, long long i, int is64) {
    return is64 ? ((const long long*)p)[i] : (long long)(((const int*)p)[i]);
}

__global__ void k_detect(const void* ei, long long E) {
    __shared__ unsigned sm[256];
    const unsigned* w = (const unsigned*)ei;
    int tid = threadIdx.x;
    int lim = (int)(E - 1 < 1024 ? E - 1 : 1024);
    unsigned acc = 0;
    for (int i = tid; i < lim; i += 256) acc |= w[2 * i + 1];
    sm[tid] = acc;
    __syncthreads();
    for (int d = 128; d; d >>= 1) {
        if (tid < d) sm[tid] |= sm[tid + d];
        __syncthreads();
    }
    if (tid == 0) g_idx64 = (sm[0] == 0u) ? 1 : 0;
}

__global__ void k_count(const void* ei, long long E) {
    int is64 = g_idx64;
    long long stride = (long long)gridDim.x * blockDim.x;
    for (long long e = (long long)blockIdx.x * blockDim.x + threadIdx.x; e < E; e += stride) {
        int dst = (int)ldidx(ei, E + e, is64);
        atomicAdd(&g_cnt[dst], 1);
    }
}

__global__ void k_scan_a(int n) {
    __shared__ int sm[SCAN_T];
    int tid = threadIdx.x;
    int base = blockIdx.x * SCAN_TILE + tid * SCAN_C;
    int s = 0;
#pragma unroll
    for (int i = 0; i < SCAN_C; i++) {
        int idx = base + i;
        if (idx < n) s += g_cnt[idx];
    }
    sm[tid] = s;
    __syncthreads();
    for (int d = SCAN_T / 2; d; d >>= 1) {
        if (tid < d) sm[tid] += sm[tid + d];
        __syncthreads();
    }
    if (tid == 0) g_bsum[blockIdx.x] = sm[0];
}

__global__ void k_scan_b(int nb) {
    __shared__ int sm[128];
    int tid = threadIdx.x;
    int v = (tid < nb) ? g_bsum[tid] : 0;
    sm[tid] = v;
    __syncthreads();
    for (int d = 1; d < 128; d <<= 1) {
        int t = (tid >= d) ? sm[tid - d] : 0;
        __syncthreads();
        sm[tid] += t;
        __syncthreads();
    }
    if (tid < nb) g_boff[tid] = sm[tid] - v;
}

__global__ void k_scan_c(int n) {
    __shared__ int sm[SCAN_T];
    int tid = threadIdx.x;
    int base = blockIdx.x * SCAN_TILE + tid * SCAN_C;
    int c[SCAN_C];
    int s = 0;
#pragma unroll
    for (int i = 0; i < SCAN_C; i++) {
        int idx = base + i;
        c[i] = (idx < n) ? g_cnt[idx] : 0;
        s += c[i];
    }
    sm[tid] = s;
    __syncthreads();
    for (int d = 1; d < SCAN_T; d <<= 1) {
        int t = (tid >= d) ? sm[tid - d] : 0;
        __syncthreads();
        sm[tid] += t;
        __syncthreads();
    }
    int run = g_boff[blockIdx.x] + sm[tid] - s;
#pragma unroll
    for (int i = 0; i < SCAN_C; i++) {
        int idx = base + i;
        if (idx < n) {
            g_rowptr[idx] = run;
            g_cursor[idx] = run;
            g_dinv[idx] = rsqrtf((float)(c[i] + 1));
            run += c[i];
        } else if (idx == n) {
            g_rowptr[n] = run;
        }
    }
}

__global__ void k_fill(const void* ei, long long E) {
    int is64 = g_idx64;
    long long stride = (long long)gridDim.x * blockDim.x;
    for (long long e = (long long)blockIdx.x * blockDim.x + threadIdx.x; e < E; e += stride) {
        int src = (int)ldidx(ei, e, is64);
        int dst = (int)ldidx(ei, E + e, is64);
        int p = atomicAdd(&g_cursor[dst], 1);
        g_srcs[p] = src;
    }
}

__device__ __forceinline__ unsigned f2h2(float a, float b) {
    __half2 h = __floats2half2_rn(a, b);
    return *(unsigned*)&h;
}

__global__ void k_wconv(const float* __restrict__ W1, const float* __restrict__ W2,
                        const float* __restrict__ f1, const float* __restrict__ f2) {
    int i = blockIdx.x * blockDim.x + threadIdx.x;
    if (i >= 448 * DF) return;
    int r = i >> 7;
    float v;
    if (r < 128) v = W1[i];
    else if (r < 256) v = W2[i - 128 * DF];
    else if (r < 384) v = f1[i - 256 * DF];
    else v = f2[i - 384 * DF];
    g_wh[i] = __float2half_rn(v);
}

__global__ void k_xconv(const float4* __restrict__ x, uint2* __restrict__ xh, int n4) {
    int stride = gridDim.x * blockDim.x;
    for (int i = blockIdx.x * blockDim.x + threadIdx.x; i < n4; i += stride) {
        float4 v = x[i];
        uint2 o;
        o.x = f2h2(v.x, v.y);
        o.y = f2h2(v.z, v.w);
        xh[i] = o;
    }
}

// ---------------- mma helpers ----------------
__device__ __forceinline__ void mma_f16(float* d, const unsigned* a, const unsigned* b) {
    asm volatile(
        "mma.sync.aligned.m16n8k16.row.col.f32.f16.f16.f32 "
        "{%0,%1,%2,%3}, {%4,%5,%6,%7}, {%8,%9}, {%0,%1,%2,%3};\n"
        : "+f"(d[0]), "+f"(d[1]), "+f"(d[2]), "+f"(d[3])
        : "r"(a[0]), "r"(a[1]), "r"(a[2]), "r"(a[3]), "r"(b[0]), "r"(b[1]));
}

__device__ __forceinline__ void ldsm_x4(unsigned& r0, unsigned& r1, unsigned& r2, unsigned& r3,
                                        unsigned addr) {
    asm volatile("ldmatrix.sync.aligned.m8n8.x4.shared.b16 {%0,%1,%2,%3}, [%4];"
                 : "=r"(r0), "=r"(r1), "=r"(r2), "=r"(r3) : "r"(addr));
}

__device__ __forceinline__ void cp16(unsigned dst, const void* src, int srcsz) {
    asm volatile("cp.async.cg.shared.global [%0], [%1], 16, %2;"
                 :: "r"(dst), "l"(src), "r"(srcsz));
}
__device__ __forceinline__ void cp16f(unsigned dst, const void* src) {
    asm volatile("cp.async.cg.shared.global [%0], [%1], 16;" :: "r"(dst), "l"(src));
}

__device__ __forceinline__ float act_apply(float v, int ACT) {
    if (ACT == 1) return v > 0.f ? v : expm1f(v);
    return v;
}

// ---------------- standalone fp16 GEMM (layer 1, A=xh) ----------------
template <int ACT>
__global__ __launch_bounds__(256, 2) void k_gemm_f16(
    const __half* __restrict__ Ah, const __half* __restrict__ Wh,
    const float* __restrict__ bias, __half* __restrict__ C, int M) {
    extern __shared__ char smem[];
    unsigned sbase = (unsigned)__cvta_generic_to_shared(smem);
    int tid = threadIdx.x;
    int lane = tid & 31, warp = tid >> 5;
    int mw = warp & 1, nw = warp >> 1;
    int rowBase = blockIdx.x * 128;
    int g = lane >> 2, tig = lane & 3;
    int laneM = lane >> 3, laneR = lane & 7;

    const unsigned* Ahu = (const unsigned*)Ah;
    const unsigned* Whu = (const unsigned*)Wh;

#pragma unroll
    for (int ch = 0; ch < 2; ch++) {
        unsigned asb = sbase + ch * CHUNK_BYTES;
        unsigned wsb = sbase + 2 * CHUNK_BYTES + ch * CHUNK_BYTES;
#pragma unroll
        for (int i = 0; i < 4; i++) {
            int id = tid + i * 256;
            int r = id >> 3, c8 = (id & 7) * 4;
            int gr = rowBase + r;
            int ok = (gr < M) ? 16 : 0;
            const unsigned* srcA = Ahu + (size_t)(ok ? gr : 0) * 64 + ch * 32 + c8;
            cp16(asb + (unsigned)(r * LDA + c8) * 4, srcA, ok);
            const unsigned* srcW = Whu + (size_t)r * 64 + ch * 32 + c8;
            cp16f(wsb + (unsigned)(r * LDA + c8) * 4, srcW);
        }
        asm volatile("cp.async.commit_group;");
    }

    float acc[4][4][4];
#pragma unroll
    for (int i = 0; i < 4; i++)
#pragma unroll
        for (int j = 0; j < 4; j++)
#pragma unroll
            for (int q = 0; q < 4; q++) acc[i][j][q] = 0.f;

#pragma unroll
    for (int ch = 0; ch < 2; ch++) {
        if (ch == 0) asm volatile("cp.async.wait_group 1;");
        else         asm volatile("cp.async.wait_group 0;");
        __syncthreads();
        unsigned asb = sbase + ch * CHUNK_BYTES;
        unsigned wsb = sbase + 2 * CHUNK_BYTES + ch * CHUNK_BYTES;

#pragma unroll
        for (int ks = 0; ks < 4; ks++) {
            int k0 = ks * 8;
            unsigned afr[4][4], bfr[2][4];
#pragma unroll
            for (int ma = 0; ma < 4; ma++) {
                int row = mw * 64 + ma * 16 + (laneM & 1) * 8 + laneR;
                unsigned a = asb + (unsigned)(row * LDA + k0 + (laneM >> 1) * 4) * 4;
                ldsm_x4(afr[ma][0], afr[ma][1], afr[ma][2], afr[ma][3], a);
            }
#pragma unroll
            for (int p = 0; p < 2; p++) {
                int row = nw * 32 + p * 16 + (laneM >> 1) * 8 + laneR;
                unsigned a = wsb + (unsigned)(row * LDA + k0 + (laneM & 1) * 4) * 4;
                ldsm_x4(bfr[p][0], bfr[p][1], bfr[p][2], bfr[p][3], a);
            }
#pragma unroll
            for (int ma = 0; ma < 4; ma++)
#pragma unroll
                for (int p = 0; p < 2; p++) {
                    mma_f16(acc[ma][2 * p + 0], afr[ma], &bfr[p][0]);
                    mma_f16(acc[ma][2 * p + 1], afr[ma], &bfr[p][2]);
                }
        }
    }

#pragma unroll
    for (int ma = 0; ma < 4; ma++) {
        int r0 = rowBase + mw * 64 + ma * 16 + g;
        int r1 = r0 + 8;
#pragma unroll
        for (int na = 0; na < 4; na++) {
            int cc = nw * 32 + na * 8 + 2 * tig;
            float b0 = bias[cc], b1 = bias[cc + 1];
            float x0 = act_apply(acc[ma][na][0] + b0, ACT);
            float x1 = act_apply(acc[ma][na][1] + b1, ACT);
            float x2 = act_apply(acc[ma][na][2] + b0, ACT);
            float x3 = act_apply(acc[ma][na][3] + b1, ACT);
            if (r0 < M) *(__half2*)(C + (size_t)r0 * DF + cc) = __floats2half2_rn(x0, x1);
            if (r1 < M) *(__half2*)(C + (size_t)r1 * DF + cc) = __floats2half2_rn(x2, x3);
        }
    }
}

// ---------------- FUSED aggregation + GEMM ----------------
// Phase 1: each warp aggregates 16 nodes (rows of this block's A tile) from zin,
//          applies aggBias (+optional relu), writes fp16 rows into smem A tile
//          (optionally also fp32 rows to zsOut). W prefetched via cp.async.
// Phase 2: C[row,:] = act(Arow @ W^T + gemmBias), fp16 out.
template <int RELU, int GACT, int WRITE_ZS>
__global__ __launch_bounds__(256, 2) void k_agg_gemm(
    const uint2* __restrict__ zin, const __half* __restrict__ Wh,
    const float* __restrict__ aggBias, const float* __restrict__ gemmBias,
    float* __restrict__ zsOut, __half* __restrict__ C, int M) {
    extern __shared__ char smem[];
    unsigned sbase = (unsigned)__cvta_generic_to_shared(smem);
    int tid = threadIdx.x;
    int lane = tid & 31, warp = tid >> 5;
    int mw = warp & 1, nw = warp >> 1;
    int rowBase = blockIdx.x * 128;
    int g = lane >> 2, tig = lane & 3;
    int laneM = lane >> 3, laneR = lane & 7;

    const unsigned* Whu = (const unsigned*)Wh;

    // prefetch W (both chunks) while we aggregate
#pragma unroll
    for (int ch = 0; ch < 2; ch++) {
        unsigned wsb = sbase + 2 * CHUNK_BYTES + ch * CHUNK_BYTES;
#pragma unroll
        for (int i = 0; i < 4; i++) {
            int id = tid + i * 256;
            int r = id >> 3, c8 = (id & 7) * 4;
            const unsigned* srcW = Whu + (size_t)r * 64 + ch * 32 + c8;
            cp16f(wsb + (unsigned)(r * LDA + c8) * 4, srcW);
        }
    }
    asm volatile("cp.async.commit_group;");

    // phase 1: aggregate this block's 128 rows into smem A tile
    float4 bb = ((const float4*)aggBias)[lane];
    int cc0 = 2 * lane;                          // u32 col within full 64-col row
    int chSel = (cc0 >= 32);
    unsigned aoff = (unsigned)(chSel ? CHUNK_BYTES : 0);
    int ccl = cc0 - (chSel ? 32 : 0);

#pragma unroll 1
    for (int t = 0; t < 16; t++) {
        int node = rowBase + warp * 16 + t;
        uint2 oz = make_uint2(0, 0);
        float4 acc = make_float4(0.f, 0.f, 0.f, 0.f);
        if (node < M) {
            float di = g_dinv[node];
            uint2 su = zin[(size_t)node * 32 + lane];
            float2 a0 = __half22float2(*(__half2*)&su.x);
            float2 a1 = __half22float2(*(__half2*)&su.y);
            float sw = di * di;
            acc.x = sw * a0.x; acc.y = sw * a0.y; acc.z = sw * a1.x; acc.w = sw * a1.y;
            int e = g_rowptr[node], end = g_rowptr[node + 1];
            for (; e + 4 <= end; e += 4) {
                int s[4];
                float wt[4];
#pragma unroll
                for (int i = 0; i < 4; i++) s[i] = g_srcs[e + i];
#pragma unroll
                for (int i = 0; i < 4; i++) wt[i] = di * g_dinv[s[i]];
                uint2 u[4];
#pragma unroll
                for (int i = 0; i < 4; i++) u[i] = zin[(size_t)s[i] * 32 + lane];
#pragma unroll
                for (int i = 0; i < 4; i++) {
                    float2 f0 = __half22float2(*(__half2*)&u[i].x);
                    float2 f1 = __half22float2(*(__half2*)&u[i].y);
                    acc.x = fmaf(wt[i], f0.x, acc.x); acc.y = fmaf(wt[i], f0.y, acc.y);
                    acc.z = fmaf(wt[i], f1.x, acc.z); acc.w = fmaf(wt[i], f1.y, acc.w);
                }
            }
            for (; e < end; e++) {
                int s = g_srcs[e];
                float wt = di * g_dinv[s];
                uint2 u = zin[(size_t)s * 32 + lane];
                float2 f0 = __half22float2(*(__half2*)&u.x);
                float2 f1 = __half22float2(*(__half2*)&u.y);
                acc.x = fmaf(wt, f0.x, acc.x); acc.y = fmaf(wt, f0.y, acc.y);
                acc.z = fmaf(wt, f1.x, acc.z); acc.w = fmaf(wt, f1.y, acc.w);
            }
            acc.x += bb.x; acc.y += bb.y; acc.z += bb.z; acc.w += bb.w;
            if (RELU) {
                acc.x = fmaxf(acc.x, 0.f); acc.y = fmaxf(acc.y, 0.f);
                acc.z = fmaxf(acc.z, 0.f); acc.w = fmaxf(acc.w, 0.f);
            }
            if (WRITE_ZS) ((float4*)zsOut)[(size_t)node * 32 + lane] = acc;
            oz.x = f2h2(acc.x, acc.y);
            oz.y = f2h2(acc.z, acc.w);
        }
        int r = warp * 16 + t;
        *(uint2*)(smem + aoff + (unsigned)(r * LDA + ccl) * 4) = oz;
    }

    asm volatile("cp.async.wait_group 0;");
    __syncthreads();

    // phase 2: GEMM from smem
    float acc[4][4][4];
#pragma unroll
    for (int i = 0; i < 4; i++)
#pragma unroll
        for (int j = 0; j < 4; j++)
#pragma unroll
            for (int q = 0; q < 4; q++) acc[i][j][q] = 0.f;

#pragma unroll
    for (int ch = 0; ch < 2; ch++) {
        unsigned asb = sbase + ch * CHUNK_BYTES;
        unsigned wsb = sbase + 2 * CHUNK_BYTES + ch * CHUNK_BYTES;
#pragma unroll
        for (int ks = 0; ks < 4; ks++) {
            int k0 = ks * 8;
            unsigned afr[4][4], bfr[2][4];
#pragma unroll
            for (int ma = 0; ma < 4; ma++) {
                int row = mw * 64 + ma * 16 + (laneM & 1) * 8 + laneR;
                unsigned a = asb + (unsigned)(row * LDA + k0 + (laneM >> 1) * 4) * 4;
                ldsm_x4(afr[ma][0], afr[ma][1], afr[ma][2], afr[ma][3], a);
            }
#pragma unroll
            for (int p = 0; p < 2; p++) {
                int row = nw * 32 + p * 16 + (laneM >> 1) * 8 + laneR;
                unsigned a = wsb + (unsigned)(row * LDA + k0 + (laneM & 1) * 4) * 4;
                ldsm_x4(bfr[p][0], bfr[p][1], bfr[p][2], bfr[p][3], a);
            }
#pragma unroll
            for (int ma = 0; ma < 4; ma++)
#pragma unroll
                for (int p = 0; p < 2; p++) {
                    mma_f16(acc[ma][2 * p + 0], afr[ma], &bfr[p][0]);
                    mma_f16(acc[ma][2 * p + 1], afr[ma], &bfr[p][2]);
                }
        }
    }

#pragma unroll
    for (int ma = 0; ma < 4; ma++) {
        int r0 = rowBase + mw * 64 + ma * 16 + g;
        int r1 = r0 + 8;
#pragma unroll
        for (int na = 0; na < 4; na++) {
            int cc = nw * 32 + na * 8 + 2 * tig;
            float b0 = gemmBias[cc], b1 = gemmBias[cc + 1];
            float x0 = act_apply(acc[ma][na][0] + b0, GACT);
            float x1 = act_apply(acc[ma][na][1] + b1, GACT);
            float x2 = act_apply(acc[ma][na][2] + b0, GACT);
            float x3 = act_apply(acc[ma][na][3] + b1, GACT);
            if (r0 < M) *(__half2*)(C + (size_t)r0 * DF + cc) = __floats2half2_rn(x0, x1);
            if (r1 < M) *(__half2*)(C + (size_t)r1 * DF + cc) = __floats2half2_rn(x2, x3);
        }
    }
}

// ---------------- fp16 final GEMM (N=64) + fused log_softmax ----------------
__global__ __launch_bounds__(256, 2) void k_gemm_lsm_f16(
    const __half* __restrict__ Ah, const __half* __restrict__ Wh,
    const float* __restrict__ bias, float* __restrict__ out, int M) {
    extern __shared__ char smem[];
    unsigned sbase = (unsigned)__cvta_generic_to_shared(smem);
    int tid = threadIdx.x;
    int lane = tid & 31, warp = tid >> 5;
    int rowBase = blockIdx.x * 128;
    int g = lane >> 2, tig = lane & 3;
    int laneM = lane >> 3, laneR = lane & 7;

    const unsigned* Ahu = (const unsigned*)Ah;
    const unsigned* Whu = (const unsigned*)Wh;
    const unsigned WOFF = 2 * CHUNK_BYTES;
    const unsigned WCH = 64 * LDA * 4;

#pragma unroll
    for (int ch = 0; ch < 2; ch++) {
        unsigned asb = sbase + ch * CHUNK_BYTES;
        unsigned wsb = sbase + WOFF + ch * WCH;
#pragma unroll
        for (int i = 0; i < 4; i++) {
            int id = tid + i * 256;
            int r = id >> 3, c8 = (id & 7) * 4;
            int gr = rowBase + r;
            int ok = (gr < M) ? 16 : 0;
            const unsigned* srcA = Ahu + (size_t)(ok ? gr : 0) * 64 + ch * 32 + c8;
            cp16(asb + (unsigned)(r * LDA + c8) * 4, srcA, ok);
        }
#pragma unroll
        for (int i = 0; i < 2; i++) {
            int id = tid + i * 256;
            int r = id >> 3, c8 = (id & 7) * 4;
            const unsigned* srcW = Whu + (size_t)r * 64 + ch * 32 + c8;
            cp16f(wsb + (unsigned)(r * LDA + c8) * 4, srcW);
        }
        asm volatile("cp.async.commit_group;");
    }

    float acc[8][4];
#pragma unroll
    for (int j = 0; j < 8; j++)
#pragma unroll
        for (int q = 0; q < 4; q++) acc[j][q] = 0.f;

#pragma unroll
    for (int ch = 0; ch < 2; ch++) {
        if (ch == 0) asm volatile("cp.async.wait_group 1;");
        else         asm volatile("cp.async.wait_group 0;");
        __syncthreads();
        unsigned asb = sbase + ch * CHUNK_BYTES;
        unsigned wsb = sbase + WOFF + ch * WCH;

#pragma unroll
        for (int ks = 0; ks < 4; ks++) {
            int k0 = ks * 8;
            unsigned afr[4], bfr[4][4];
            {
                int row = warp * 16 + (laneM & 1) * 8 + laneR;
                unsigned a = asb + (unsigned)(row * LDA + k0 + (laneM >> 1) * 4) * 4;
                ldsm_x4(afr[0], afr[1], afr[2], afr[3], a);
            }
#pragma unroll
            for (int p = 0; p < 4; p++) {
                int row = p * 16 + (laneM >> 1) * 8 + laneR;
                unsigned a = wsb + (unsigned)(row * LDA + k0 + (laneM & 1) * 4) * 4;
                ldsm_x4(bfr[p][0], bfr[p][1], bfr[p][2], bfr[p][3], a);
            }
#pragma unroll
            for (int p = 0; p < 4; p++) {
                mma_f16(acc[2 * p + 0], afr, &bfr[p][0]);
                mma_f16(acc[2 * p + 1], afr, &bfr[p][2]);
            }
        }
    }

    float v0[16], v1[16];
#pragma unroll
    for (int na = 0; na < 8; na++) {
        int cc = na * 8 + 2 * tig;
        float b0 = bias[cc], b1 = bias[cc + 1];
        v0[na * 2 + 0] = acc[na][0] + b0;
        v0[na * 2 + 1] = acc[na][1] + b1;
        v1[na * 2 + 0] = acc[na][2] + b0;
        v1[na * 2 + 1] = acc[na][3] + b1;
    }
    float m0 = v0[0], m1 = v1[0];
#pragma unroll
    for (int i = 1; i < 16; i++) { m0 = fmaxf(m0, v0[i]); m1 = fmaxf(m1, v1[i]); }
#pragma unroll
    for (int d = 1; d < 4; d <<= 1) {
        m0 = fmaxf(m0, __shfl_xor_sync(0xffffffffu, m0, d));
        m1 = fmaxf(m1, __shfl_xor_sync(0xffffffffu, m1, d));
    }
    float s0 = 0.f, s1 = 0.f;
#pragma unroll
    for (int i = 0; i < 16; i++) { s0 += expf(v0[i] - m0); s1 += expf(v1[i] - m1); }
#pragma unroll
    for (int d = 1; d < 4; d <<= 1) {
        s0 += __shfl_xor_sync(0xffffffffu, s0, d);
        s1 += __shfl_xor_sync(0xffffffffu, s1, d);
    }
    float ls0 = m0 + logf(s0), ls1 = m1 + logf(s1);

    int r0 = rowBase + warp * 16 + g;
    int r1 = r0 + 8;
#pragma unroll
    for (int na = 0; na < 8; na++) {
        int cc = na * 8 + 2 * tig;
        if (r0 < M) {
            float2 o = make_float2(v0[na * 2] - ls0, v0[na * 2 + 1] - ls0);
            *(float2*)(out + (size_t)r0 * 64 + cc) = o;
        }
        if (r1 < M) {
            float2 o = make_float2(v1[na * 2] - ls1, v1[na * 2 + 1] - ls1);
            *(float2*)(out + (size_t)r1 * 64 + cc) = o;
        }
    }
}

// ---------------- launcher ----------------
extern "C" void kernel_launch(void* const* d_in, const int* in_sizes, int n_in,
                              void* d_out, int out_size) {
    const float* x    = (const float*)d_in[0];
    const void*  ei   = d_in[1];
    const float* W1   = (const float*)d_in[2];
    const float* b1   = (const float*)d_in[3];
    const float* W2   = (const float*)d_in[4];
    const float* b2   = (const float*)d_in[5];
    const float* fcW1 = (const float*)d_in[6];
    const float* fcb1 = (const float*)d_in[7];
    const float* fcW2 = (const float*)d_in[8];
    const float* fcb2 = (const float*)d_in[9];

    int N = in_sizes[0] / DF;
    long long E = (long long)in_sizes[1] / 2;

    float *zsb, *resb, *zb;
    __half *z0h, *z1h, *zsh, *wh;
    int* cntp;
    cudaGetSymbolAddress((void**)&z0h, g_z0h);
    cudaGetSymbolAddress((void**)&z1h, g_z1h);
    cudaGetSymbolAddress((void**)&zsh, g_zsh);
    cudaGetSymbolAddress((void**)&wh,  g_wh);
    cudaGetSymbolAddress((void**)&zsb, g_zs);
    cudaGetSymbolAddress((void**)&resb, g_res);
    cudaGetSymbolAddress((void**)&zb,  g_zerob);
    cudaGetSymbolAddress((void**)&cntp, g_cnt);

    const __half* whW1 = wh;
    const __half* whW2 = wh + 128 * DF;
    const __half* whF1 = wh + 256 * DF;
    const __half* whF2 = wh + 384 * DF;

    float* zs_out;
    float* res_out;
    long long need_both = (long long)N * (DF + 64);
    if ((long long)out_size >= need_both) {
        zs_out = (float*)d_out;
        res_out = (float*)d_out + (size_t)N * DF;
    } else if (out_size == N * 64) {
        zs_out = zsb;
        res_out = (float*)d_out;
    } else {
        zs_out = (float*)d_out;
        res_out = resb;
    }

    int nb_e = (int)((E + 255) / 256);
    int nb_g = (N + 127) / 128;
    int nb_s = (N + 1 + SCAN_TILE - 1) / SCAN_TILE;
    int nb_x = (N * 32 + 255) / 256;

    static cudaStream_t s2 = nullptr;
    static cudaEvent_t evFork = nullptr, evJoin = nullptr;
    if (s2 == nullptr) {
        cudaStreamCreateWithFlags(&s2, cudaStreamNonBlocking);
        cudaEventCreateWithFlags(&evFork, cudaEventDisableTiming);
        cudaEventCreateWithFlags(&evJoin, cudaEventDisableTiming);
        cudaFuncSetAttribute(k_gemm_f16<0>, cudaFuncAttributeMaxDynamicSharedMemorySize, GEMM_SMEM);
        cudaFuncSetAttribute(k_agg_gemm<1, 0, 0>, cudaFuncAttributeMaxDynamicSharedMemorySize, GEMM_SMEM);
        cudaFuncSetAttribute(k_agg_gemm<0, 1, 1>, cudaFuncAttributeMaxDynamicSharedMemorySize, GEMM_SMEM);
        cudaFuncSetAttribute(k_gemm_lsm_f16, cudaFuncAttributeMaxDynamicSharedMemorySize, LSM_SMEM);
    }

    // fork: preprocessing on s2; conversions + gemm1 on default stream
    cudaEventRecord(evFork, 0);
    cudaStreamWaitEvent(s2, evFork, 0);

    k_detect<<<1, 256, 0, s2>>>(ei, E);
    cudaMemsetAsync(cntp, 0, (size_t)N * sizeof(int), s2);
    k_count<<<nb_e, 256, 0, s2>>>(ei, E);
    k_scan_a<<<nb_s, SCAN_T, 0, s2>>>(N);
    k_scan_b<<<1, 128, 0, s2>>>(nb_s);
    k_scan_c<<<nb_s, SCAN_T, 0, s2>>>(N);
    k_fill<<<nb_e, 256, 0, s2>>>(ei, E);
    cudaEventRecord(evJoin, s2);

    k_wconv<<<(448 * DF + 255) / 256, 256>>>(W1, W2, fcW1, fcW2);
    k_xconv<<<nb_x < 4096 ? nb_x : 4096, 256>>>((const float4*)x, (uint2*)zsh, N * 32);
    k_gemm_f16<0><<<nb_g, 256, GEMM_SMEM>>>(zsh, whW1, zb, z0h, N);

    cudaStreamWaitEvent(0, evJoin, 0);

    // fused layer 1 agg + layer 2 GEMM:
    //   z1 = relu(agg(z0h)+b1) (smem only) ; z1h <- z1 @ W2^T
    k_agg_gemm<1, 0, 0><<<nb_g, 256, GEMM_SMEM>>>(
        (const uint2*)z0h, whW2, b1, zb, nullptr, z1h, N);

    // fused layer 2 agg + fc1:
    //   zs = agg(z1h)+b2 -> fp32 output ; z0h <- elu(zs @ fcW1^T + fcb1)
    k_agg_gemm<0, 1, 1><<<nb_g, 256, GEMM_SMEM>>>(
        (const uint2*)z1h, whF1, b2, fcb1, zs_out, z0h, N);

    // res = log_softmax(z0h @ fcW2^T + fcb2)
    k_gemm_lsm_f16<<<nb_g, 256, LSM_SMEM>>>(z0h, whF2, fcb2, res_out, N);
}

// round 14
// speedup vs baseline: 1.0006x; 1.0006x over previous
#include <cuda_runtime.h>
#include <cuda_fp16.h>
#include <math.h>

#define NN_MAX 100000
#define EE_MAX 1600000
#define DF 128

#define SCAN_T 256
#define SCAN_C 4
#define SCAN_TILE (SCAN_T * SCAN_C)
#define SCAN_NBMAX ((NN_MAX + 1 + SCAN_TILE - 1) / SCAN_TILE + 1)

// ---------------- scratch (device globals: no allocation allowed) ----------------
__device__ int   g_idx64;
__device__ int   g_cnt[NN_MAX];
__device__ int   g_rowptr[NN_MAX + 1];
__device__ int   g_cursor[NN_MAX];
__device__ int   g_srcs[EE_MAX];
__device__ float g_dinv[NN_MAX];
__device__ int   g_bsum[SCAN_NBMAX];
__device__ int   g_bflag[SCAN_NBMAX];
__device__ __half g_z0h[(size_t)NN_MAX * DF];
__device__ __half g_z1h[(size_t)NN_MAX * DF];
__device__ __half g_zsh[(size_t)NN_MAX * DF];
__device__ __half g_wh[448 * DF];               // W1|W2|fcW1|fcW2 as fp16
__device__ float g_zs[(size_t)NN_MAX * DF];
__device__ float g_res[(size_t)NN_MAX * 64];
__device__ float g_zerob[DF];   // stays zero (bss)

// ---------------- helpers ----------------
__device__ __forceinline__ long long ldidx(const void* p, long long i, int is64) {
    return is64 ? ((const long long*)p)[i] : (long long)(((const int*)p)[i]);
}

// detect dtype + zero the scan flags (runs first on the preproc stream)
__global__ void k_detect(const void* ei, long long E) {
    __shared__ unsigned sm[256];
    const unsigned* w = (const unsigned*)ei;
    int tid = threadIdx.x;
    for (int i = tid; i < SCAN_NBMAX; i += 256) g_bflag[i] = 0;
    int lim = (int)(E - 1 < 1024 ? E - 1 : 1024);
    unsigned acc = 0;
    for (int i = tid; i < lim; i += 256) acc |= w[2 * i + 1];
    sm[tid] = acc;
    __syncthreads();
    for (int d = 128; d; d >>= 1) {
        if (tid < d) sm[tid] |= sm[tid + d];
        __syncthreads();
    }
    if (tid == 0) g_idx64 = (sm[0] == 0u) ? 1 : 0;
}

__global__ void k_count(const void* ei, long long E) {
    int is64 = g_idx64;
    long long stride = (long long)gridDim.x * blockDim.x;
    for (long long e = (long long)blockIdx.x * blockDim.x + threadIdx.x; e < E; e += stride) {
        int dst = (int)ldidx(ei, E + e, is64);
        atomicAdd(&g_cnt[dst], 1);
    }
}

// ---------------- single-pass chip-wide exclusive scan (publish + parallel lookback) ----
__global__ void k_scan_f(int n) {
    __shared__ int sm[SCAN_T];
    __shared__ int sp[SCAN_T];
    int tid = threadIdx.x;
    int bid = blockIdx.x;
    int base = bid * SCAN_TILE + tid * SCAN_C;
    int c[SCAN_C];
    int s = 0;
#pragma unroll
    for (int i = 0; i < SCAN_C; i++) {
        int idx = base + i;
        c[i] = (idx < n) ? g_cnt[idx] : 0;
        s += c[i];
    }
    sm[tid] = s;
    __syncthreads();
    // block-wide inclusive scan (Hillis-Steele)
    for (int d = 1; d < SCAN_T; d <<= 1) {
        int t = (tid >= d) ? sm[tid - d] : 0;
        __syncthreads();
        sm[tid] += t;
        __syncthreads();
    }
    // publish this block's total
    if (tid == 0) {
        g_bsum[bid] = sm[SCAN_T - 1];
        __threadfence();
        g_bflag[bid] = 1;
    }
    // parallel lookback: sum all predecessor block totals
    int p = 0;
    volatile int* vflag = (volatile int*)g_bflag;
    volatile int* vsum = (volatile int*)g_bsum;
    for (int t = tid; t < bid; t += SCAN_T) {
        while (vflag[t] == 0) {}
        p += vsum[t];
    }
    sp[tid] = p;
    __syncthreads();
    for (int d = SCAN_T / 2; d; d >>= 1) {
        if (tid < d) sp[tid] += sp[tid + d];
        __syncthreads();
    }
    int run = sp[0] + sm[tid] - s;   // exclusive prefix for this thread
#pragma unroll
    for (int i = 0; i < SCAN_C; i++) {
        int idx = base + i;
        if (idx < n) {
            g_rowptr[idx] = run;
            g_cursor[idx] = run;
            g_dinv[idx] = rsqrtf((float)(c[i] + 1));
            run += c[i];
        } else if (idx == n) {
            g_rowptr[n] = run;
        }
    }
}

__global__ void k_fill(const void* ei, long long E) {
    int is64 = g_idx64;
    long long stride = (long long)gridDim.x * blockDim.x;
    for (long long e = (long long)blockIdx.x * blockDim.x + threadIdx.x; e < E; e += stride) {
        int src = (int)ldidx(ei, e, is64);
        int dst = (int)ldidx(ei, E + e, is64);
        int p = atomicAdd(&g_cursor[dst], 1);
        g_srcs[p] = src;
    }
}

// weights -> fp16 (W1 rows 0-127, W2 128-255, fcW1 256-383, fcW2 384-447)
__global__ void k_wconv(const float* __restrict__ W1, const float* __restrict__ W2,
                        const float* __restrict__ f1, const float* __restrict__ f2) {
    int i = blockIdx.x * blockDim.x + threadIdx.x;
    if (i >= 448 * DF) return;
    int r = i >> 7;
    float v;
    if (r < 128) v = W1[i];
    else if (r < 256) v = W2[i - 128 * DF];
    else if (r < 384) v = f1[i - 256 * DF];
    else v = f2[i - 384 * DF];
    g_wh[i] = __float2half_rn(v);
}

// ---------------- fp16 tensor-core GEMM (W already fp16) ----------------
#define LDA 36

__device__ __forceinline__ unsigned f2h2(float a, float b) {
    __half2 h = __floats2half2_rn(a, b);
    return *(unsigned*)&h;
}

__device__ __forceinline__ void mma_f16(float* d, const unsigned* a, const unsigned* b) {
    asm volatile(
        "mma.sync.aligned.m16n8k16.row.col.f32.f16.f16.f32 "
        "{%0,%1,%2,%3}, {%4,%5,%6,%7}, {%8,%9}, {%0,%1,%2,%3};\n"
        : "+f"(d[0]), "+f"(d[1]), "+f"(d[2]), "+f"(d[3])
        : "r"(a[0]), "r"(a[1]), "r"(a[2]), "r"(a[3]), "r"(b[0]), "r"(b[1]));
}

__device__ __forceinline__ float act_apply(float v, int ACT) {
    if (ACT == 1) return v > 0.f ? v : expm1f(v);
    return v;
}

// INH: A source half (else float). OUTH: store half (else float). Wh fp16.
template <int ACT, int INH, int OUTH>
__global__ __launch_bounds__(256, 2) void k_gemm_f16(
    const void* __restrict__ Av, const __half* __restrict__ Wh,
    const float* __restrict__ bias, void* __restrict__ Cv, int M) {
    __shared__ unsigned As[128 * LDA];
    __shared__ unsigned Ws[128 * LDA];
    int tid = threadIdx.x;
    int lane = tid & 31, warp = tid >> 5;
    int mw = warp & 1, nw = warp >> 1;
    int rowBase = blockIdx.x * 128;
    int g = lane >> 2, tig = lane & 3;

    float acc[4][4][4];
#pragma unroll
    for (int i = 0; i < 4; i++)
#pragma unroll
        for (int j = 0; j < 4; j++)
#pragma unroll
            for (int q = 0; q < 4; q++) acc[i][j][q] = 0.f;

#pragma unroll
    for (int ch = 0; ch < 2; ch++) {
        int kh = ch * 64;
#pragma unroll
        for (int i = 0; i < 4; i++) {
            int id = tid + i * 256;
            int r = id >> 3, c8 = (id & 7) * 4;
            if (INH) {
                uint4 u = make_uint4(0, 0, 0, 0);
                if (rowBase + r < M)
                    u = *(const uint4*)((const unsigned*)Av + (size_t)(rowBase + r) * (DF / 2) + kh / 2 + c8);
                *(uint4*)&As[r * LDA + c8] = u;
            } else {
                float4 v0 = make_float4(0.f, 0.f, 0.f, 0.f), v1 = v0;
                if (rowBase + r < M) {
                    const float* ap = (const float*)Av + (size_t)(rowBase + r) * DF + kh + c8 * 2;
                    v0 = *(const float4*)(ap);
                    v1 = *(const float4*)(ap + 4);
                }
                *(uint4*)&As[r * LDA + c8] = make_uint4(
                    f2h2(v0.x, v0.y), f2h2(v0.z, v0.w), f2h2(v1.x, v1.y), f2h2(v1.z, v1.w));
            }
            uint4 uw = *(const uint4*)((const unsigned*)Wh + (size_t)r * (DF / 2) + kh / 2 + c8);
            *(uint4*)&Ws[r * LDA + c8] = uw;
        }
        __syncthreads();

#pragma unroll
        for (int ks = 0; ks < 4; ks++) {
            int k0 = ks * 8;
            unsigned afr[4][4], bfr[4][2];
#pragma unroll
            for (int ma = 0; ma < 4; ma++) {
                int row = mw * 64 + ma * 16;
                afr[ma][0] = As[(row + g) * LDA + k0 + tig];
                afr[ma][1] = As[(row + g + 8) * LDA + k0 + tig];
                afr[ma][2] = As[(row + g) * LDA + k0 + tig + 4];
                afr[ma][3] = As[(row + g + 8) * LDA + k0 + tig + 4];
            }
#pragma unroll
            for (int na = 0; na < 4; na++) {
                int colw = nw * 32 + na * 8;
                bfr[na][0] = Ws[(colw + g) * LDA + k0 + tig];
                bfr[na][1] = Ws[(colw + g) * LDA + k0 + tig + 4];
            }
#pragma unroll
            for (int ma = 0; ma < 4; ma++)
#pragma unroll
                for (int na = 0; na < 4; na++) mma_f16(acc[ma][na], afr[ma], bfr[na]);
        }
        __syncthreads();
    }

#pragma unroll
    for (int ma = 0; ma < 4; ma++) {
        int r0 = rowBase + mw * 64 + ma * 16 + g;
        int r1 = r0 + 8;
#pragma unroll
        for (int na = 0; na < 4; na++) {
            int cc = nw * 32 + na * 8 + 2 * tig;
            float b0 = bias[cc], b1 = bias[cc + 1];
            float x0 = act_apply(acc[ma][na][0] + b0, ACT);
            float x1 = act_apply(acc[ma][na][1] + b1, ACT);
            float x2 = act_apply(acc[ma][na][2] + b0, ACT);
            float x3 = act_apply(acc[ma][na][3] + b1, ACT);
            if (OUTH) {
                __half* C = (__half*)Cv;
                if (r0 < M) *(__half2*)(C + (size_t)r0 * DF + cc) = __floats2half2_rn(x0, x1);
                if (r1 < M) *(__half2*)(C + (size_t)r1 * DF + cc) = __floats2half2_rn(x2, x3);
            } else {
                float* C = (float*)Cv;
                if (r0 < M) *(float2*)(C + (size_t)r0 * DF + cc) = make_float2(x0, x1);
                if (r1 < M) *(float2*)(C + (size_t)r1 * DF + cc) = make_float2(x2, x3);
            }
        }
    }
}

// ---------------- fp16 final GEMM (N=64) + fused log_softmax ----------------
__global__ __launch_bounds__(256, 2) void k_gemm_lsm_f16(
    const __half* __restrict__ A, const __half* __restrict__ Wh,
    const float* __restrict__ bias, float* __restrict__ out, int M) {
    __shared__ unsigned As[128 * LDA];
    __shared__ unsigned Ws[64 * LDA];
    int tid = threadIdx.x;
    int lane = tid & 31, warp = tid >> 5;
    int rowBase = blockIdx.x * 128;
    int g = lane >> 2, tig = lane & 3;

    float acc[8][4];
#pragma unroll
    for (int j = 0; j < 8; j++)
#pragma unroll
        for (int q = 0; q < 4; q++) acc[j][q] = 0.f;

#pragma unroll
    for (int ch = 0; ch < 2; ch++) {
        int kh = ch * 64;
#pragma unroll
        for (int i = 0; i < 4; i++) {
            int id = tid + i * 256;
            int r = id >> 3, c8 = (id & 7) * 4;
            uint4 u = make_uint4(0, 0, 0, 0);
            if (rowBase + r < M)
                u = *(const uint4*)((const unsigned*)A + (size_t)(rowBase + r) * (DF / 2) + kh / 2 + c8);
            *(uint4*)&As[r * LDA + c8] = u;
        }
#pragma unroll
        for (int i = 0; i < 2; i++) {
            int id = tid + i * 256;
            int r = id >> 3, c8 = (id & 7) * 4;
            uint4 uw = *(const uint4*)((const unsigned*)Wh + (size_t)r * (DF / 2) + kh / 2 + c8);
            *(uint4*)&Ws[r * LDA + c8] = uw;
        }
        __syncthreads();

#pragma unroll
        for (int ks = 0; ks < 4; ks++) {
            int k0 = ks * 8;
            unsigned afr[4], bfr[8][2];
            int row = warp * 16;
            afr[0] = As[(row + g) * LDA + k0 + tig];
            afr[1] = As[(row + g + 8) * LDA + k0 + tig];
            afr[2] = As[(row + g) * LDA + k0 + tig + 4];
            afr[3] = As[(row + g + 8) * LDA + k0 + tig + 4];
#pragma unroll
            for (int na = 0; na < 8; na++) {
                int colw = na * 8;
                bfr[na][0] = Ws[(colw + g) * LDA + k0 + tig];
                bfr[na][1] = Ws[(colw + g) * LDA + k0 + tig + 4];
            }
#pragma unroll
            for (int na = 0; na < 8; na++) mma_f16(acc[na], afr, bfr[na]);
        }
        __syncthreads();
    }

    float v0[16], v1[16];
#pragma unroll
    for (int na = 0; na < 8; na++) {
        int cc = na * 8 + 2 * tig;
        float b0 = bias[cc], b1 = bias[cc + 1];
        v0[na * 2 + 0] = acc[na][0] + b0;
        v0[na * 2 + 1] = acc[na][1] + b1;
        v1[na * 2 + 0] = acc[na][2] + b0;
        v1[na * 2 + 1] = acc[na][3] + b1;
    }
    float m0 = v0[0], m1 = v1[0];
#pragma unroll
    for (int i = 1; i < 16; i++) { m0 = fmaxf(m0, v0[i]); m1 = fmaxf(m1, v1[i]); }
#pragma unroll
    for (int d = 1; d < 4; d <<= 1) {
        m0 = fmaxf(m0, __shfl_xor_sync(0xffffffffu, m0, d));
        m1 = fmaxf(m1, __shfl_xor_sync(0xffffffffu, m1, d));
    }
    float s0 = 0.f, s1 = 0.f;
#pragma unroll
    for (int i = 0; i < 16; i++) { s0 += expf(v0[i] - m0); s1 += expf(v1[i] - m1); }
#pragma unroll
    for (int d = 1; d < 4; d <<= 1) {
        s0 += __shfl_xor_sync(0xffffffffu, s0, d);
        s1 += __shfl_xor_sync(0xffffffffu, s1, d);
    }
    float ls0 = m0 + logf(s0), ls1 = m1 + logf(s1);

    int r0 = rowBase + warp * 16 + g;
    int r1 = r0 + 8;
#pragma unroll
    for (int na = 0; na < 8; na++) {
        int cc = na * 8 + 2 * tig;
        if (r0 < M) {
            float2 o = make_float2(v0[na * 2] - ls0, v0[na * 2 + 1] - ls0);
            *(float2*)(out + (size_t)r0 * 64 + cc) = o;
        }
        if (r1 < M) {
            float2 o = make_float2(v1[na * 2] - ls1, v1[na * 2 + 1] - ls1);
            *(float2*)(out + (size_t)r1 * 64 + cc) = o;
        }
    }
}

// ---------------- aggregation over fp16 features ----------------
__global__ void k_agg_h(const uint2* __restrict__ zin, float* __restrict__ outf,
                        __half* __restrict__ outh, const float* __restrict__ bias,
                        int n, int relu) {
    int w = (blockIdx.x * blockDim.x + threadIdx.x) >> 5;
    int lane = threadIdx.x & 31;
    if (w >= n) return;
    float di = g_dinv[w];
    uint2 su = zin[(size_t)w * 32 + lane];
    float2 a0 = __half22float2(*(__half2*)&su.x);
    float2 a1 = __half22float2(*(__half2*)&su.y);
    float sw = di * di;
    float4 acc;
    acc.x = sw * a0.x; acc.y = sw * a0.y; acc.z = sw * a1.x; acc.w = sw * a1.y;
    int e = g_rowptr[w], end = g_rowptr[w + 1];
    for (; e + 4 <= end; e += 4) {
        int s[4];
        float wt[4];
#pragma unroll
        for (int i = 0; i < 4; i++) s[i] = g_srcs[e + i];
#pragma unroll
        for (int i = 0; i < 4; i++) wt[i] = di * g_dinv[s[i]];
        uint2 u[4];
#pragma unroll
        for (int i = 0; i < 4; i++) u[i] = zin[(size_t)s[i] * 32 + lane];
#pragma unroll
        for (int i = 0; i < 4; i++) {
            float2 f0 = __half22float2(*(__half2*)&u[i].x);
            float2 f1 = __half22float2(*(__half2*)&u[i].y);
            acc.x = fmaf(wt[i], f0.x, acc.x); acc.y = fmaf(wt[i], f0.y, acc.y);
            acc.z = fmaf(wt[i], f1.x, acc.z); acc.w = fmaf(wt[i], f1.y, acc.w);
        }
    }
    for (; e < end; e++) {
        int s = g_srcs[e];
        float wt = di * g_dinv[s];
        uint2 u = zin[(size_t)s * 32 + lane];
        float2 f0 = __half22float2(*(__half2*)&u.x);
        float2 f1 = __half22float2(*(__half2*)&u.y);
        acc.x = fmaf(wt, f0.x, acc.x); acc.y = fmaf(wt, f0.y, acc.y);
        acc.z = fmaf(wt, f1.x, acc.z); acc.w = fmaf(wt, f1.y, acc.w);
    }
    float4 b = ((const float4*)bias)[lane];
    acc.x += b.x; acc.y += b.y; acc.z += b.z; acc.w += b.w;
    if (relu) {
        acc.x = fmaxf(acc.x, 0.f); acc.y = fmaxf(acc.y, 0.f);
        acc.z = fmaxf(acc.z, 0.f); acc.w = fmaxf(acc.w, 0.f);
    }
    if (outf) ((float4*)outf)[(size_t)w * 32 + lane] = acc;
    if (outh) {
        uint2 o;
        __half2 h0 = __floats2half2_rn(acc.x, acc.y);
        __half2 h1 = __floats2half2_rn(acc.z, acc.w);
        o.x = *(unsigned*)&h0; o.y = *(unsigned*)&h1;
        ((uint2*)outh)[(size_t)w * 32 + lane] = o;
    }
}

// ---------------- launcher ----------------
extern "C" void kernel_launch(void* const* d_in, const int* in_sizes, int n_in,
                              void* d_out, int out_size) {
    const float* x    = (const float*)d_in[0];
    const void*  ei   = d_in[1];
    const float* W1   = (const float*)d_in[2];
    const float* b1   = (const float*)d_in[3];
    const float* W2   = (const float*)d_in[4];
    const float* b2   = (const float*)d_in[5];
    const float* fcW1 = (const float*)d_in[6];
    const float* fcb1 = (const float*)d_in[7];
    const float* fcW2 = (const float*)d_in[8];
    const float* fcb2 = (const float*)d_in[9];

    int N = in_sizes[0] / DF;
    long long E = (long long)in_sizes[1] / 2;

    float *zsb, *resb, *zb;
    __half *z0h, *z1h, *zsh, *wh;
    int* cntp;
    cudaGetSymbolAddress((void**)&z0h, g_z0h);
    cudaGetSymbolAddress((void**)&z1h, g_z1h);
    cudaGetSymbolAddress((void**)&zsh, g_zsh);
    cudaGetSymbolAddress((void**)&wh,  g_wh);
    cudaGetSymbolAddress((void**)&zsb, g_zs);
    cudaGetSymbolAddress((void**)&resb, g_res);
    cudaGetSymbolAddress((void**)&zb,  g_zerob);
    cudaGetSymbolAddress((void**)&cntp, g_cnt);

    const __half* whW1 = wh;
    const __half* whW2 = wh + 128 * DF;
    const __half* whF1 = wh + 256 * DF;
    const __half* whF2 = wh + 384 * DF;

    // Output layout: tuple (zs [N,128], res [N,64]) concatenated.
    float* zs_out;
    float* res_out;
    long long need_both = (long long)N * (DF + 64);
    if ((long long)out_size >= need_both) {
        zs_out = (float*)d_out;
        res_out = (float*)d_out + (size_t)N * DF;
    } else if (out_size == N * 64) {
        zs_out = zsb;
        res_out = (float*)d_out;
    } else {
        zs_out = (float*)d_out;
        res_out = resb;
    }

    int nb_e = (int)((E + 255) / 256);
    int nb_w = (N * 32 + 255) / 256;
    int nb_g = (N + 127) / 128;
    int nb_s = (N + 1 + SCAN_TILE - 1) / SCAN_TILE;

    static cudaStream_t s2 = nullptr;
    static cudaEvent_t evFork = nullptr, evJoin = nullptr;
    if (s2 == nullptr) {
        cudaStreamCreateWithFlags(&s2, cudaStreamNonBlocking);
        cudaEventCreateWithFlags(&evFork, cudaEventDisableTiming);
        cudaEventCreateWithFlags(&evJoin, cudaEventDisableTiming);
    }

    // fork: preprocessing branch on s2, gemm branch on default stream
    cudaEventRecord(evFork, 0);
    cudaStreamWaitEvent(s2, evFork, 0);

    // s2: graph preprocessing (CSR build; single-pass scan)
    k_detect<<<1, 256, 0, s2>>>(ei, E);
    cudaMemsetAsync(cntp, 0, (size_t)N * sizeof(int), s2);
    k_count<<<nb_e, 256, 0, s2>>>(ei, E);
    k_scan_f<<<nb_s, SCAN_T, 0, s2>>>(N);
    k_fill<<<nb_e, 256, 0, s2>>>(ei, E);
    cudaEventRecord(evJoin, s2);

    // default: weight conversion + gemm1 (independent of graph build)
    k_wconv<<<(448 * DF + 255) / 256, 256>>>(W1, W2, fcW1, fcW2);
    k_gemm_f16<0, 0, 1><<<nb_g, 256>>>(x, whW1, zb, z0h, N);

    // join
    cudaStreamWaitEvent(0, evJoin, 0);

    // layer 1: z1h = relu(agg(x @ W1^T) + b1)
    k_agg_h<<<nb_w, 256>>>((const uint2*)z0h, nullptr, z1h, b1, N, 1);

    // layer 2: zs = agg(z1 @ W2^T) + b2
    k_gemm_f16<0, 1, 1><<<nb_g, 256>>>(z1h, whW2, zb, z0h, N);
    k_agg_h<<<nb_w, 256>>>((const uint2*)z0h, zs_out, zsh, b2, N, 0);

    // projection: h = elu(zs @ fcW1^T + fcb1); res = log_softmax(h @ fcW2^T + fcb2)
    k_gemm_f16<1, 1, 1><<<nb_g, 256>>>(zsh, whF1, fcb1, z0h, N);
    k_gemm_lsm_f16<<<nb_g, 256>>>(z0h, whF2, fcb2, res_out, N);
}

// round 15
// speedup vs baseline: 1.4647x; 1.4638x over previous
#include <cuda_runtime.h>
#include <cuda_fp16.h>
#include <math.h>

#define NN_MAX 100000
#define EE_MAX 1600000
#define DF 128

#define SCAN_T 256
#define SCAN_C 4
#define SCAN_TILE (SCAN_T * SCAN_C)
#define SCAN_NBMAX ((NN_MAX + 1 + SCAN_TILE - 1) / SCAN_TILE + 1)

// ---------------- scratch (device globals: no allocation allowed) ----------------
__device__ int   g_idx64;
__device__ int   g_cnt[NN_MAX];
__device__ int   g_rowptr[NN_MAX + 1];
__device__ int   g_cursor[NN_MAX];
__device__ int   g_srcs[EE_MAX];
__device__ float g_dinv[NN_MAX];
__device__ int   g_bsum[SCAN_NBMAX];
__device__ int   g_boff[SCAN_NBMAX];
__device__ __half g_z0h[(size_t)NN_MAX * DF];
__device__ __half g_z1h[(size_t)NN_MAX * DF];
__device__ __half g_zsh[(size_t)NN_MAX * DF];
__device__ __half g_wh[448 * DF];               // W1|W2|fcW1|fcW2 as fp16
__device__ float g_zs[(size_t)NN_MAX * DF];
__device__ float g_res[(size_t)NN_MAX * 64];
__device__ float g_zerob[DF];   // stays zero (bss)

// ---------------- helpers ----------------
__device__ __forceinline__ long long ldidx(const void* p, long long i, int is64) {
    return is64 ? ((const long long*)p)[i] : (long long)(((const int*)p)[i]);
}

__global__ void k_detect(const void* ei, long long E) {
    __shared__ unsigned sm[256];
    const unsigned* w = (const unsigned*)ei;
    int tid = threadIdx.x;
    int lim = (int)(E - 1 < 1024 ? E - 1 : 1024);
    unsigned acc = 0;
    for (int i = tid; i < lim; i += 256) acc |= w[2 * i + 1];
    sm[tid] = acc;
    __syncthreads();
    for (int d = 128; d; d >>= 1) {
        if (tid < d) sm[tid] |= sm[tid + d];
        __syncthreads();
    }
    if (tid == 0) g_idx64 = (sm[0] == 0u) ? 1 : 0;
}

__global__ void k_count(const void* ei, long long E) {
    int is64 = g_idx64;
    long long stride = (long long)gridDim.x * blockDim.x;
    for (long long e = (long long)blockIdx.x * blockDim.x + threadIdx.x; e < E; e += stride) {
        int dst = (int)ldidx(ei, E + e, is64);
        atomicAdd(&g_cnt[dst], 1);
    }
}

// ---------------- 3-phase chip-wide exclusive scan of g_cnt ----------------
__global__ void k_scan_a(int n) {
    __shared__ int sm[SCAN_T];
    int tid = threadIdx.x;
    int base = blockIdx.x * SCAN_TILE + tid * SCAN_C;
    int s = 0;
#pragma unroll
    for (int i = 0; i < SCAN_C; i++) {
        int idx = base + i;
        if (idx < n) s += g_cnt[idx];
    }
    sm[tid] = s;
    __syncthreads();
    for (int d = SCAN_T / 2; d; d >>= 1) {
        if (tid < d) sm[tid] += sm[tid + d];
        __syncthreads();
    }
    if (tid == 0) g_bsum[blockIdx.x] = sm[0];
}

__global__ void k_scan_b(int nb) {
    __shared__ int sm[128];
    int tid = threadIdx.x;
    int v = (tid < nb) ? g_bsum[tid] : 0;
    sm[tid] = v;
    __syncthreads();
    for (int d = 1; d < 128; d <<= 1) {
        int t = (tid >= d) ? sm[tid - d] : 0;
        __syncthreads();
        sm[tid] += t;
        __syncthreads();
    }
    if (tid < nb) g_boff[tid] = sm[tid] - v;
}

__global__ void k_scan_c(int n) {
    __shared__ int sm[SCAN_T];
    int tid = threadIdx.x;
    int base = blockIdx.x * SCAN_TILE + tid * SCAN_C;
    int c[SCAN_C];
    int s = 0;
#pragma unroll
    for (int i = 0; i < SCAN_C; i++) {
        int idx = base + i;
        c[i] = (idx < n) ? g_cnt[idx] : 0;
        s += c[i];
    }
    sm[tid] = s;
    __syncthreads();
    for (int d = 1; d < SCAN_T; d <<= 1) {
        int t = (tid >= d) ? sm[tid - d] : 0;
        __syncthreads();
        sm[tid] += t;
        __syncthreads();
    }
    int run = g_boff[blockIdx.x] + sm[tid] - s;
#pragma unroll
    for (int i = 0; i < SCAN_C; i++) {
        int idx = base + i;
        if (idx < n) {
            g_rowptr[idx] = run;
            g_cursor[idx] = run;
            g_dinv[idx] = rsqrtf((float)(c[i] + 1));
            run += c[i];
        } else if (idx == n) {
            g_rowptr[n] = run;
        }
    }
}

__global__ void k_fill(const void* ei, long long E) {
    int is64 = g_idx64;
    long long stride = (long long)gridDim.x * blockDim.x;
    for (long long e = (long long)blockIdx.x * blockDim.x + threadIdx.x; e < E; e += stride) {
        int src = (int)ldidx(ei, e, is64);
        int dst = (int)ldidx(ei, E + e, is64);
        int p = atomicAdd(&g_cursor[dst], 1);
        g_srcs[p] = src;
    }
}

// weights -> fp16 (W1 rows 0-127, W2 128-255, fcW1 256-383, fcW2 384-447)
__global__ void k_wconv(const float* __restrict__ W1, const float* __restrict__ W2,
                        const float* __restrict__ f1, const float* __restrict__ f2) {
    int i = blockIdx.x * blockDim.x + threadIdx.x;
    if (i >= 448 * DF) return;
    int r = i >> 7;
    float v;
    if (r < 128) v = W1[i];
    else if (r < 256) v = W2[i - 128 * DF];
    else if (r < 384) v = f1[i - 256 * DF];
    else v = f2[i - 384 * DF];
    g_wh[i] = __float2half_rn(v);
}

// ---------------- fp16 tensor-core GEMM (W already fp16) ----------------
#define LDA 36

__device__ __forceinline__ unsigned f2h2(float a, float b) {
    __half2 h = __floats2half2_rn(a, b);
    return *(unsigned*)&h;
}

__device__ __forceinline__ void mma_f16(float* d, const unsigned* a, const unsigned* b) {
    asm volatile(
        "mma.sync.aligned.m16n8k16.row.col.f32.f16.f16.f32 "
        "{%0,%1,%2,%3}, {%4,%5,%6,%7}, {%8,%9}, {%0,%1,%2,%3};\n"
        : "+f"(d[0]), "+f"(d[1]), "+f"(d[2]), "+f"(d[3])
        : "r"(a[0]), "r"(a[1]), "r"(a[2]), "r"(a[3]), "r"(b[0]), "r"(b[1]));
}

__device__ __forceinline__ float act_apply(float v, int ACT) {
    if (ACT == 1) return v > 0.f ? v : expm1f(v);
    return v;
}

// INH: A source half (else float). OUTH: store half (else float). Wh fp16.
template <int ACT, int INH, int OUTH>
__global__ __launch_bounds__(256, 2) void k_gemm_f16(
    const void* __restrict__ Av, const __half* __restrict__ Wh,
    const float* __restrict__ bias, void* __restrict__ Cv, int M) {
    __shared__ unsigned As[128 * LDA];
    __shared__ unsigned Ws[128 * LDA];
    int tid = threadIdx.x;
    int lane = tid & 31, warp = tid >> 5;
    int mw = warp & 1, nw = warp >> 1;
    int rowBase = blockIdx.x * 128;
    int g = lane >> 2, tig = lane & 3;

    float acc[4][4][4];
#pragma unroll
    for (int i = 0; i < 4; i++)
#pragma unroll
        for (int j = 0; j < 4; j++)
#pragma unroll
            for (int q = 0; q < 4; q++) acc[i][j][q] = 0.f;

#pragma unroll
    for (int ch = 0; ch < 2; ch++) {
        int kh = ch * 64;
#pragma unroll
        for (int i = 0; i < 4; i++) {
            int id = tid + i * 256;
            int r = id >> 3, c8 = (id & 7) * 4;
            if (INH) {
                uint4 u = make_uint4(0, 0, 0, 0);
                if (rowBase + r < M)
                    u = *(const uint4*)((const unsigned*)Av + (size_t)(rowBase + r) * (DF / 2) + kh / 2 + c8);
                *(uint4*)&As[r * LDA + c8] = u;
            } else {
                float4 v0 = make_float4(0.f, 0.f, 0.f, 0.f), v1 = v0;
                if (rowBase + r < M) {
                    const float* ap = (const float*)Av + (size_t)(rowBase + r) * DF + kh + c8 * 2;
                    v0 = *(const float4*)(ap);
                    v1 = *(const float4*)(ap + 4);
                }
                *(uint4*)&As[r * LDA + c8] = make_uint4(
                    f2h2(v0.x, v0.y), f2h2(v0.z, v0.w), f2h2(v1.x, v1.y), f2h2(v1.z, v1.w));
            }
            uint4 uw = *(const uint4*)((const unsigned*)Wh + (size_t)r * (DF / 2) + kh / 2 + c8);
            *(uint4*)&Ws[r * LDA + c8] = uw;
        }
        __syncthreads();

#pragma unroll
        for (int ks = 0; ks < 4; ks++) {
            int k0 = ks * 8;
            unsigned afr[4][4], bfr[4][2];
#pragma unroll
            for (int ma = 0; ma < 4; ma++) {
                int row = mw * 64 + ma * 16;
                afr[ma][0] = As[(row + g) * LDA + k0 + tig];
                afr[ma][1] = As[(row + g + 8) * LDA + k0 + tig];
                afr[ma][2] = As[(row + g) * LDA + k0 + tig + 4];
                afr[ma][3] = As[(row + g + 8) * LDA + k0 + tig + 4];
            }
#pragma unroll
            for (int na = 0; na < 4; na++) {
                int colw = nw * 32 + na * 8;
                bfr[na][0] = Ws[(colw + g) * LDA + k0 + tig];
                bfr[na][1] = Ws[(colw + g) * LDA + k0 + tig + 4];
            }
#pragma unroll
            for (int ma = 0; ma < 4; ma++)
#pragma unroll
                for (int na = 0; na < 4; na++) mma_f16(acc[ma][na], afr[ma], bfr[na]);
        }
        __syncthreads();
    }

#pragma unroll
    for (int ma = 0; ma < 4; ma++) {
        int r0 = rowBase + mw * 64 + ma * 16 + g;
        int r1 = r0 + 8;
#pragma unroll
        for (int na = 0; na < 4; na++) {
            int cc = nw * 32 + na * 8 + 2 * tig;
            float b0 = bias[cc], b1 = bias[cc + 1];
            float x0 = act_apply(acc[ma][na][0] + b0, ACT);
            float x1 = act_apply(acc[ma][na][1] + b1, ACT);
            float x2 = act_apply(acc[ma][na][2] + b0, ACT);
            float x3 = act_apply(acc[ma][na][3] + b1, ACT);
            if (OUTH) {
                __half* C = (__half*)Cv;
                if (r0 < M) *(__half2*)(C + (size_t)r0 * DF + cc) = __floats2half2_rn(x0, x1);
                if (r1 < M) *(__half2*)(C + (size_t)r1 * DF + cc) = __floats2half2_rn(x2, x3);
            } else {
                float* C = (float*)Cv;
                if (r0 < M) *(float2*)(C + (size_t)r0 * DF + cc) = make_float2(x0, x1);
                if (r1 < M) *(float2*)(C + (size_t)r1 * DF + cc) = make_float2(x2, x3);
            }
        }
    }
}

// ---------------- fp16 final GEMM (N=64) + fused log_softmax ----------------
__global__ __launch_bounds__(256, 2) void k_gemm_lsm_f16(
    const __half* __restrict__ A, const __half* __restrict__ Wh,
    const float* __restrict__ bias, float* __restrict__ out, int M) {
    __shared__ unsigned As[128 * LDA];
    __shared__ unsigned Ws[64 * LDA];
    int tid = threadIdx.x;
    int lane = tid & 31, warp = tid >> 5;
    int rowBase = blockIdx.x * 128;
    int g = lane >> 2, tig = lane & 3;

    float acc[8][4];
#pragma unroll
    for (int j = 0; j < 8; j++)
#pragma unroll
        for (int q = 0; q < 4; q++) acc[j][q] = 0.f;

#pragma unroll
    for (int ch = 0; ch < 2; ch++) {
        int kh = ch * 64;
#pragma unroll
        for (int i = 0; i < 4; i++) {
            int id = tid + i * 256;
            int r = id >> 3, c8 = (id & 7) * 4;
            uint4 u = make_uint4(0, 0, 0, 0);
            if (rowBase + r < M)
                u = *(const uint4*)((const unsigned*)A + (size_t)(rowBase + r) * (DF / 2) + kh / 2 + c8);
            *(uint4*)&As[r * LDA + c8] = u;
        }
#pragma unroll
        for (int i = 0; i < 2; i++) {
            int id = tid + i * 256;
            int r = id >> 3, c8 = (id & 7) * 4;
            uint4 uw = *(const uint4*)((const unsigned*)Wh + (size_t)r * (DF / 2) + kh / 2 + c8);
            *(uint4*)&Ws[r * LDA + c8] = uw;
        }
        __syncthreads();

#pragma unroll
        for (int ks = 0; ks < 4; ks++) {
            int k0 = ks * 8;
            unsigned afr[4], bfr[8][2];
            int row = warp * 16;
            afr[0] = As[(row + g) * LDA + k0 + tig];
            afr[1] = As[(row + g + 8) * LDA + k0 + tig];
            afr[2] = As[(row + g) * LDA + k0 + tig + 4];
            afr[3] = As[(row + g + 8) * LDA + k0 + tig + 4];
#pragma unroll
            for (int na = 0; na < 8; na++) {
                int colw = na * 8;
                bfr[na][0] = Ws[(colw + g) * LDA + k0 + tig];
                bfr[na][1] = Ws[(colw + g) * LDA + k0 + tig + 4];
            }
#pragma unroll
            for (int na = 0; na < 8; na++) mma_f16(acc[na], afr, bfr[na]);
        }
        __syncthreads();
    }

    float v0[16], v1[16];
#pragma unroll
    for (int na = 0; na < 8; na++) {
        int cc = na * 8 + 2 * tig;
        float b0 = bias[cc], b1 = bias[cc + 1];
        v0[na * 2 + 0] = acc[na][0] + b0;
        v0[na * 2 + 1] = acc[na][1] + b1;
        v1[na * 2 + 0] = acc[na][2] + b0;
        v1[na * 2 + 1] = acc[na][3] + b1;
    }
    float m0 = v0[0], m1 = v1[0];
#pragma unroll
    for (int i = 1; i < 16; i++) { m0 = fmaxf(m0, v0[i]); m1 = fmaxf(m1, v1[i]); }
#pragma unroll
    for (int d = 1; d < 4; d <<= 1) {
        m0 = fmaxf(m0, __shfl_xor_sync(0xffffffffu, m0, d));
        m1 = fmaxf(m1, __shfl_xor_sync(0xffffffffu, m1, d));
    }
    float s0 = 0.f, s1 = 0.f;
#pragma unroll
    for (int i = 0; i < 16; i++) { s0 += expf(v0[i] - m0); s1 += expf(v1[i] - m1); }
#pragma unroll
    for (int d = 1; d < 4; d <<= 1) {
        s0 += __shfl_xor_sync(0xffffffffu, s0, d);
        s1 += __shfl_xor_sync(0xffffffffu, s1, d);
    }
    float ls0 = m0 + logf(s0), ls1 = m1 + logf(s1);

    int r0 = rowBase + warp * 16 + g;
    int r1 = r0 + 8;
#pragma unroll
    for (int na = 0; na < 8; na++) {
        int cc = na * 8 + 2 * tig;
        if (r0 < M) {
            float2 o = make_float2(v0[na * 2] - ls0, v0[na * 2 + 1] - ls0);
            *(float2*)(out + (size_t)r0 * 64 + cc) = o;
        }
        if (r1 < M) {
            float2 o = make_float2(v1[na * 2] - ls1, v1[na * 2 + 1] - ls1);
            *(float2*)(out + (size_t)r1 * 64 + cc) = o;
        }
    }
}

// ---------------- aggregation over fp16 features ----------------
__global__ void k_agg_h(const uint2* __restrict__ zin, float* __restrict__ outf,
                        __half* __restrict__ outh, const float* __restrict__ bias,
                        int n, int relu) {
    int w = (blockIdx.x * blockDim.x + threadIdx.x) >> 5;
    int lane = threadIdx.x & 31;
    if (w >= n) return;
    float di = g_dinv[w];
    uint2 su = zin[(size_t)w * 32 + lane];
    float2 a0 = __half22float2(*(__half2*)&su.x);
    float2 a1 = __half22float2(*(__half2*)&su.y);
    float sw = di * di;
    float4 acc;
    acc.x = sw * a0.x; acc.y = sw * a0.y; acc.z = sw * a1.x; acc.w = sw * a1.y;
    int e = g_rowptr[w], end = g_rowptr[w + 1];
    for (; e + 4 <= end; e += 4) {
        int s[4];
        float wt[4];
#pragma unroll
        for (int i = 0; i < 4; i++) s[i] = g_srcs[e + i];
#pragma unroll
        for (int i = 0; i < 4; i++) wt[i] = di * g_dinv[s[i]];
        uint2 u[4];
#pragma unroll
        for (int i = 0; i < 4; i++) u[i] = zin[(size_t)s[i] * 32 + lane];
#pragma unroll
        for (int i = 0; i < 4; i++) {
            float2 f0 = __half22float2(*(__half2*)&u[i].x);
            float2 f1 = __half22float2(*(__half2*)&u[i].y);
            acc.x = fmaf(wt[i], f0.x, acc.x); acc.y = fmaf(wt[i], f0.y, acc.y);
            acc.z = fmaf(wt[i], f1.x, acc.z); acc.w = fmaf(wt[i], f1.y, acc.w);
        }
    }
    for (; e < end; e++) {
        int s = g_srcs[e];
        float wt = di * g_dinv[s];
        uint2 u = zin[(size_t)s * 32 + lane];
        float2 f0 = __half22float2(*(__half2*)&u.x);
        float2 f1 = __half22float2(*(__half2*)&u.y);
        acc.x = fmaf(wt, f0.x, acc.x); acc.y = fmaf(wt, f0.y, acc.y);
        acc.z = fmaf(wt, f1.x, acc.z); acc.w = fmaf(wt, f1.y, acc.w);
    }
    float4 b = ((const float4*)bias)[lane];
    acc.x += b.x; acc.y += b.y; acc.z += b.z; acc.w += b.w;
    if (relu) {
        acc.x = fmaxf(acc.x, 0.f); acc.y = fmaxf(acc.y, 0.f);
        acc.z = fmaxf(acc.z, 0.f); acc.w = fmaxf(acc.w, 0.f);
    }
    if (outf) ((float4*)outf)[(size_t)w * 32 + lane] = acc;
    if (outh) {
        uint2 o;
        __half2 h0 = __floats2half2_rn(acc.x, acc.y);
        __half2 h1 = __floats2half2_rn(acc.z, acc.w);
        o.x = *(unsigned*)&h0; o.y = *(unsigned*)&h1;
        ((uint2*)outh)[(size_t)w * 32 + lane] = o;
    }
}

// ---------------- launcher ----------------
extern "C" void kernel_launch(void* const* d_in, const int* in_sizes, int n_in,
                              void* d_out, int out_size) {
    const float* x    = (const float*)d_in[0];
    const void*  ei   = d_in[1];
    const float* W1   = (const float*)d_in[2];
    const float* b1   = (const float*)d_in[3];
    const float* W2   = (const float*)d_in[4];
    const float* b2   = (const float*)d_in[5];
    const float* fcW1 = (const float*)d_in[6];
    const float* fcb1 = (const float*)d_in[7];
    const float* fcW2 = (const float*)d_in[8];
    const float* fcb2 = (const float*)d_in[9];

    int N = in_sizes[0] / DF;
    long long E = (long long)in_sizes[1] / 2;

    float *zsb, *resb, *zb;
    __half *z0h, *z1h, *zsh, *wh;
    int* cntp;
    cudaGetSymbolAddress((void**)&z0h, g_z0h);
    cudaGetSymbolAddress((void**)&z1h, g_z1h);
    cudaGetSymbolAddress((void**)&zsh, g_zsh);
    cudaGetSymbolAddress((void**)&wh,  g_wh);
    cudaGetSymbolAddress((void**)&zsb, g_zs);
    cudaGetSymbolAddress((void**)&resb, g_res);
    cudaGetSymbolAddress((void**)&zb,  g_zerob);
    cudaGetSymbolAddress((void**)&cntp, g_cnt);

    const __half* whW1 = wh;
    const __half* whW2 = wh + 128 * DF;
    const __half* whF1 = wh + 256 * DF;
    const __half* whF2 = wh + 384 * DF;

    // Output layout: tuple (zs [N,128], res [N,64]) concatenated.
    float* zs_out;
    float* res_out;
    long long need_both = (long long)N * (DF + 64);
    if ((long long)out_size >= need_both) {
        zs_out = (float*)d_out;
        res_out = (float*)d_out + (size_t)N * DF;
    } else if (out_size == N * 64) {
        zs_out = zsb;
        res_out = (float*)d_out;
    } else {
        zs_out = (float*)d_out;
        res_out = resb;
    }

    // edge kernels: grid-stride, 2 edges per thread (same code, fewer blocks)
    int nb_e = (int)((E + 511) / 512);
    int nb_w = (N * 32 + 255) / 256;
    int nb_g = (N + 127) / 128;
    int nb_s = (N + 1 + SCAN_TILE - 1) / SCAN_TILE;

    static cudaStream_t s2 = nullptr;
    static cudaEvent_t evFork = nullptr, evJoin = nullptr;
    if (s2 == nullptr) {
        cudaStreamCreateWithFlags(&s2, cudaStreamNonBlocking);
        cudaEventCreateWithFlags(&evFork, cudaEventDisableTiming);
        cudaEventCreateWithFlags(&evJoin, cudaEventDisableTiming);
    }

    // fork: preprocessing branch on s2, gemm branch on default stream
    cudaEventRecord(evFork, 0);
    cudaStreamWaitEvent(s2, evFork, 0);

    // s2: graph preprocessing (CSR build)
    k_detect<<<1, 256, 0, s2>>>(ei, E);
    cudaMemsetAsync(cntp, 0, (size_t)N * sizeof(int), s2);
    k_count<<<nb_e, 256, 0, s2>>>(ei, E);
    k_scan_a<<<nb_s, SCAN_T, 0, s2>>>(N);
    k_scan_b<<<1, 128, 0, s2>>>(nb_s);
    k_scan_c<<<nb_s, SCAN_T, 0, s2>>>(N);
    k_fill<<<nb_e, 256, 0, s2>>>(ei, E);
    cudaEventRecord(evJoin, s2);

    // default: weight conversion + gemm1 (independent of graph build)
    k_wconv<<<(448 * DF + 255) / 256, 256>>>(W1, W2, fcW1, fcW2);
    k_gemm_f16<0, 0, 1><<<nb_g, 256>>>(x, whW1, zb, z0h, N);

    // join
    cudaStreamWaitEvent(0, evJoin, 0);

    // layer 1: z1h = relu(agg(x @ W1^T) + b1)
    k_agg_h<<<nb_w, 256>>>((const uint2*)z0h, nullptr, z1h, b1, N, 1);

    // layer 2: zs = agg(z1 @ W2^T) + b2
    k_gemm_f16<0, 1, 1><<<nb_g, 256>>>(z1h, whW2, zb, z0h, N);
    k_agg_h<<<nb_w, 256>>>((const uint2*)z0h, zs_out, zsh, b2, N, 0);

    // projection: h = elu(zs @ fcW1^T + fcb1); res = log_softmax(h @ fcW2^T + fcb2)
    k_gemm_f16<1, 1, 1><<<nb_g, 256>>>(zsh, whF1, fcb1, z0h, N);
    k_gemm_lsm_f16<<<nb_g, 256>>>(z0h, whF2, fcb2, res_out, N);
}